// round 3
// baseline (speedup 1.0000x reference)
#include <cuda_runtime.h>
#include <cuda_bf16.h>
#include <cstdint>

#define IMG   4096
#define OUT   4097
#define TX    128
#define TY    24
#define XP    (TX + 5)   // 133  x-tile pitch (floats)
#define XR    (TY + 5)   // 29   x-tile rows
#define HP    (TX + 3)   // 131  hist-tile pitch (u64)
#define HR    (TY + 3)   // 27   hist-tile rows
#define OPLANE (OUT * OUT)
#define HTY   (TY / 2)   // 12 rows per thread

typedef unsigned long long u64;
typedef unsigned int       u32;

// predicated packed add: if (pm == P) acc += v  (two fp32 lanes at once)
#define PRED_ADD2(acc, pm, P, v)                                              \
    asm("{ .reg .pred p; setp.eq.u32 p, %1, %2; @p add.rn.f32x2 %0, %0, %3; }" \
        : "+l"(acc) : "r"(pm), "n"(P), "l"(v))

#define ADD2(d, a, b)                                                         \
    asm("add.rn.f32x2 %0, %1, %2;" : "=l"(d) : "l"(a), "l"(b))

#define FMA2(d, a, b, c)                                                      \
    asm("fma.rn.f32x2 %0, %1, %2, %3;" : "=l"(d) : "l"(a), "l"(b), "l"(c))

// route one hist row (4 packed pixels) into rs[4] (accumulating)
static __device__ __forceinline__ void accum_row(const u64* __restrict__ p, u64 rs[4]) {
#pragma unroll
    for (int j = 0; j < 4; ++j) {
        u64 h  = p[j];
        u32 pm = (u32)h & 3u;           // pair index in low 2 bits of lo lane
        PRED_ADD2(rs[0], pm, 0, h);
        PRED_ADD2(rs[1], pm, 1, h);
        PRED_ADD2(rs[2], pm, 2, h);
        PRED_ADD2(rs[3], pm, 3, h);
    }
}

__global__ __launch_bounds__(256, 5)
void sift_fused3_kernel(const float* __restrict__ x, float* __restrict__ out)
{
    __shared__ float xs[XR * XP];
    __shared__ u64   hs[HR * HP];

    const int tid = threadIdx.x;
    const int ox0 = blockIdx.x * TX;
    const int oy0 = blockIdx.y * TY;

    // ---- phase 1: load x tile, zero-padded halo
    for (int e = tid; e < XR * XP; e += 256) {
        int r  = e / XP;
        int c  = e - r * XP;
        int gy = oy0 - 3 + r;
        int gx = ox0 - 3 + c;
        float v = 0.0f;
        if ((unsigned)gy < (unsigned)IMG && (unsigned)gx < (unsigned)IMG)
            v = x[gy * IMG + gx];
        xs[e] = v;
    }
    __syncthreads();

    // ---- phase 2: sobel -> octant argmax -> pre-routed packed pair {even,odd}
    for (int e = tid; e < HR * HP; e += 256) {
        int hy = e / HP;
        int hx = e - hy * HP;
        int gy = oy0 - 2 + hy;
        int gx = ox0 - 2 + hx;
        u64 pv = 0ull;
        if ((unsigned)gy < (unsigned)IMG && (unsigned)gx < (unsigned)IMG) {
            const float* p = xs + hy * XP + hx;   // top-left of 3x3
            float a00 = p[0],      a01 = p[1],          a02 = p[2];
            float a10 = p[XP],     a12 = p[XP + 2];
            float a20 = p[2 * XP], a21 = p[2 * XP + 1], a22 = p[2 * XP + 2];
            float dx = (a02 + 2.0f * a12 + a22) - (a00 + 2.0f * a10 + a20);
            float dy = (a20 + 2.0f * a21 + a22) - (a00 + 2.0f * a01 + a02);
            float mag = sqrtf(dx * dx + dy * dy);
            // octant of atan2(dy,dx): boundaries at k*45deg; tie rules match
            // strict-> first-occurrence argmax of the 8 cosine projections.
            int   q3  = (dy < 0.0f) ? 4 : 0;
            float dx1 = q3 ? -dx : dx;
            float dy1 = q3 ? -dy : dy;
            int   q2  = (dx1 < 0.0f) ? 2 : 0;
            float dx2 = q2 ? dy1  : dx1;
            float dy2 = q2 ? -dx1 : dy1;
            int   q1  = (dy2 > dx2) ? 1 : 0;
            int   idx = q3 + q2 + q1;
            u32 magb = __float_as_uint(mag) & 0xFFFFFFFCu;
            u32 pm   = (u32)(idx >> 1);
            u32 lo, hi;
            if (idx & 1) { lo = pm;        hi = magb; }
            else         { lo = magb | pm; hi = 0u;   }
            pv = ((u64)hi << 32) | lo;
        }
        hs[e] = pv;
    }
    __syncthreads();

    // ---- phase 3: 4x4 box sum, vertical sliding window, 4 packed-pair channels
    const int tx   = tid & (TX - 1);
    const int q    = tid >> 7;              // 0/1 -> tile half in y
    const int ox   = ox0 + tx;
    const int oy_s = oy0 + q * HTY;
    const bool oxok = (ox < OUT);
    const u64* hb = hs + tx;
    const int hy0 = q * HTY;

    const u64 NEG1 = 0xBF800000BF800000ull;  // {-1.0f, -1.0f}

    u64 row[4][4];
    u64 acc[4];
#pragma unroll
    for (int pp = 0; pp < 4; ++pp) acc[pp] = 0ull;
#pragma unroll
    for (int k = 0; k < 4; ++k) {
#pragma unroll
        for (int pp = 0; pp < 4; ++pp) row[k][pp] = 0ull;
        accum_row(hb + (hy0 + k) * HP, row[k]);
#pragma unroll
        for (int pp = 0; pp < 4; ++pp) ADD2(acc[pp], acc[pp], row[k][pp]);
    }

#pragma unroll 4
    for (int i = 0; i < HTY; ++i) {
        int oy = oy_s + i;
        if (oxok && oy < OUT) {
            int base = oy * OUT + ox;
#pragma unroll
            for (int pp = 0; pp < 4; ++pp) {
                u32 lo = (u32)acc[pp];
                u32 hi = (u32)(acc[pp] >> 32);
                out[(2 * pp)     * OPLANE + base] = __uint_as_float(lo);
                out[(2 * pp + 1) * OPLANE + base] = __uint_as_float(hi);
            }
        }
        if (i < HTY - 1) {
            const int k = i & 3;
            // acc -= outgoing ring row
#pragma unroll
            for (int pp = 0; pp < 4; ++pp)
                FMA2(acc[pp], row[k][pp], NEG1, acc[pp]);
            // route incoming row directly into the ring slot
#pragma unroll
            for (int pp = 0; pp < 4; ++pp) row[k][pp] = 0ull;
            accum_row(hb + (hy0 + 4 + i) * HP, row[k]);
            // acc += incoming
#pragma unroll
            for (int pp = 0; pp < 4; ++pp)
                ADD2(acc[pp], acc[pp], row[k][pp]);
        }
    }
}

extern "C" void kernel_launch(void* const* d_in, const int* in_sizes, int n_in,
                              void* d_out, int out_size)
{
    (void)in_sizes; (void)n_in; (void)out_size;
    const float* x = (const float*)d_in[0];
    float* out = (float*)d_out;
    dim3 grid((OUT + TX - 1) / TX, (OUT + TY - 1) / TY);  // 33 x 171
    sift_fused3_kernel<<<grid, 256>>>(x, out);
}